// round 15
// baseline (speedup 1.0000x reference)
#include <cuda_runtime.h>
#include <cuda_bf16.h>
#include <cstdint>
#include <math.h>

#define N3 3072
#define NX 1024
#define EPSV 0.001f
#define NIT 18

// Scratch (device globals; no allocation allowed)
__device__ __align__(16) __nv_bfloat16 g_XThi[N3 * N3]; // X^T in bf16 (hi)
__device__ __align__(16) __nv_bfloat16 g_XTlo[N3 * N3]; // residual (lo)
__device__ float g_Ea[NX * NX];   // X1^T X1, lower tiles
__device__ float g_Eb[NX * NX];   // X3^T X3, lower tiles
__device__ float g_H22[NX * NX];  // X2^T X2 + eps I, full (mirrored)
__device__ float g_E[NX * NX];
__device__ float g_pre[NX];
__device__ float g_eps[NX];
__device__ float g_invd[NX];
__device__ float g_t1[N3];
__device__ float g_s[N3];
__device__ float g_pp[24][NX];
__device__ float g_r[2][NX];
__device__ unsigned g_barc;       // persistent-kernel grid barrier counter

__device__ __forceinline__ unsigned smem_u32(const void* p) {
    unsigned a;
    asm("{ .reg .u64 t; cvta.to.shared.u64 t, %1; cvt.u32.u64 %0, t; }" : "=r"(a) : "l"(p));
    return a;
}

__device__ __forceinline__ float warp_sum(float v) {
#pragma unroll
    for (int o = 16; o; o >>= 1) v += __shfl_xor_sync(0xffffffffu, v, o);
    return v;
}

// ---------------------------------------------------------------------------
// K0: transpose X -> XT and split fp32 = bf16 hi + bf16 lo
// ---------------------------------------------------------------------------
__global__ __launch_bounds__(256) void transpose_split(const float* __restrict__ X) {
    __shared__ float ts[32][33];
    const int bx = blockIdx.x * 32, by = blockIdx.y * 32;
    const int tx = threadIdx.x, ty = threadIdx.y;
#pragma unroll
    for (int j = 0; j < 4; j++)
        ts[ty + 8 * j][tx] = X[(size_t)(by + ty + 8 * j) * N3 + bx + tx];
    __syncthreads();
#pragma unroll
    for (int j = 0; j < 4; j++) {
        int c = bx + ty + 8 * j;
        int k = by + tx;
        float v = ts[tx][ty + 8 * j];
        __nv_bfloat16 hi = __float2bfloat16(v);
        float lo = v - __bfloat162float(hi);
        g_XThi[(size_t)c * N3 + k] = hi;
        g_XTlo[(size_t)c * N3 + k] = __float2bfloat16(lo);
    }
}

// ---------------------------------------------------------------------------
// K1: bf16 split GEMM via base-ISA mma.sync (m16n8k16) + ldmatrix.
// 108 CTAs = 36 lower tiles x {Ea, Eb, H22}. C = X'^T X' over K = 3*3072
// (hi*hi, hi*lo, lo*hi). Per CTA: 128x128 tile, KC=64 double-buffered SMEM,
// rows padded to 144B (conflict-free ldmatrix). 8 warps = 2x4, warp 64x32.
// ---------------------------------------------------------------------------
#define KC 64
#define RSB 144                    // row stride bytes (64 bf16 = 128B + 16 pad)
#define TILEB (128 * RSB)          // 18432 B per buffer
#define OFA(b) ((b) * TILEB)
#define OFB(b) (2 * TILEB + (b) * TILEB)
#define DSMEM_SZ (4 * TILEB)       // 73728 B

__device__ __forceinline__ void load_tile(char* dst,
                                          const __nv_bfloat16* __restrict__ src,
                                          int rowbase, int k0, int tid) {
    const int c = tid & 7, r0 = tid >> 3;
#pragma unroll
    for (int p = 0; p < 4; p++) {
        int r = r0 + p * 32;
        uint4 v = *(const uint4*)(src + (size_t)(rowbase + r) * N3 + k0 + c * 8);
        *(uint4*)(dst + r * RSB + c * 16) = v;
    }
}

#define LDSM_X4(r0_, r1_, r2_, r3_, addr) \
    asm volatile("ldmatrix.sync.aligned.m8n8.x4.shared.b16 {%0,%1,%2,%3}, [%4];" \
        : "=r"(r0_), "=r"(r1_), "=r"(r2_), "=r"(r3_) : "r"(addr))
#define LDSM_X2(r0_, r1_, addr) \
    asm volatile("ldmatrix.sync.aligned.m8n8.x2.shared.b16 {%0,%1}, [%2];" \
        : "=r"(r0_), "=r"(r1_) : "r"(addr))
#define MMA16816(c_, a0_, a1_, a2_, a3_, b0_, b1_) \
    asm volatile("mma.sync.aligned.m16n8k16.row.col.f32.bf16.bf16.f32 " \
        "{%0,%1,%2,%3}, {%4,%5,%6,%7}, {%8,%9}, {%0,%1,%2,%3};" \
        : "+f"((c_)[0]), "+f"((c_)[1]), "+f"((c_)[2]), "+f"((c_)[3]) \
        : "r"(a0_), "r"(a1_), "r"(a2_), "r"(a3_), "r"(b0_), "r"(b1_))

__global__ __launch_bounds__(256, 1) void mma_gemm() {
    extern __shared__ char dsm[];
    const int z = blockIdx.x;
    const int kind = z / 36;
    const int t = z - kind * 36;
    int ti = 0;
    while ((ti + 1) * (ti + 2) / 2 <= t) ti++;
    const int tj = t - ti * (ti + 1) / 2;
    const int co = (kind == 0) ? 0 : (kind == 1 ? 2048 : 1024);

    const int tid = threadIdx.x;
    const int wid = tid >> 5, lane = tid & 31;
    const int mo = (wid >> 2) * 64;   // warp m offset (0 or 64)
    const int no = (wid & 3) * 32;    // warp n offset (0,32,64,96)
    const unsigned sb = smem_u32(dsm);

    const int rowA = co + ti * 128;
    const int rowB = co + tj * 128;

    // per-lane ldmatrix address components
    const unsigned aRow = (unsigned)((mo + (lane & 15)) * RSB + (lane >> 4) * 16);
    const unsigned bRow = (unsigned)((no + (lane & 7)) * RSB + ((lane >> 3) & 1) * 16);

    float acc[4][4][4];
#pragma unroll
    for (int i = 0; i < 4; i++)
#pragma unroll
        for (int j = 0; j < 4; j++)
#pragma unroll
            for (int r = 0; r < 4; r++) acc[i][j][r] = 0.f;

    load_tile(dsm + OFA(0), g_XThi, rowA, 0, tid);
    load_tile(dsm + OFB(0), g_XThi, rowB, 0, tid);
    __syncthreads();

    int buf = 0;
    for (int c = 0; c < 144; c++) {
        if (c + 1 < 144) {
            const int cn = c + 1;
            const int split = cn / 48;
            const int kc = (cn - split * 48) * KC;
            const __nv_bfloat16* a = (split == 2) ? g_XTlo : g_XThi;
            const __nv_bfloat16* b = (split == 1) ? g_XTlo : g_XThi;
            load_tile(dsm + OFA(buf ^ 1), a, rowA, kc, tid);
            load_tile(dsm + OFB(buf ^ 1), b, rowB, kc, tid);
        }
        const unsigned abase = sb + OFA(buf) + aRow;
        const unsigned bbase = sb + OFB(buf) + bRow;
#pragma unroll
        for (int ks = 0; ks < 4; ks++) {
            unsigned a0[4], a1[4], a2[4], a3[4];
#pragma unroll
            for (int mt = 0; mt < 4; mt++)
                LDSM_X4(a0[mt], a1[mt], a2[mt], a3[mt],
                        abase + mt * 16 * RSB + ks * 32);
            unsigned b0[4], b1[4];
#pragma unroll
            for (int nt = 0; nt < 4; nt++)
                LDSM_X2(b0[nt], b1[nt], bbase + nt * 8 * RSB + ks * 32);
#pragma unroll
            for (int mt = 0; mt < 4; mt++)
#pragma unroll
                for (int nt = 0; nt < 4; nt++)
                    MMA16816(acc[mt][nt], a0[mt], a1[mt], a2[mt], a3[mt],
                             b0[nt], b1[nt]);
        }
        __syncthreads();
        buf ^= 1;
    }

    // Epilogue. d-frag mapping: rows (lane>>2, +8), cols 2*(lane&3), +1.
    const int gi0 = ti * 128 + mo;
    const int gj0 = tj * 128 + no;
#pragma unroll
    for (int mt = 0; mt < 4; mt++) {
#pragma unroll
        for (int nt = 0; nt < 4; nt++) {
#pragma unroll
            for (int half = 0; half < 2; half++) {
                int r = gi0 + mt * 16 + (lane >> 2) + half * 8;
                int cc = gj0 + nt * 8 + (lane & 3) * 2;
                float v0 = acc[mt][nt][half * 2];
                float v1 = acc[mt][nt][half * 2 + 1];
                if (kind < 2) {
                    float* C = kind ? g_Eb : g_Ea;
                    C[r * NX + cc] = v0;
                    C[r * NX + cc + 1] = v1;
                } else {
                    if (r == cc) v0 += EPSV;
                    if (r == cc + 1) v1 += EPSV;
                    if (ti != tj) {
                        g_H22[r * NX + cc] = v0;
                        g_H22[r * NX + cc + 1] = v1;
                        g_H22[cc * NX + r] = v0;
                        g_H22[(cc + 1) * NX + r] = v1;
                    } else {
                        if (r >= cc) {
                            g_H22[r * NX + cc] = v0;
                            if (r > cc) g_H22[cc * NX + r] = v0;
                        }
                        if (r >= cc + 1) {
                            g_H22[r * NX + cc + 1] = v1;
                            if (r > cc + 1) g_H22[(cc + 1) * NX + r] = v1;
                        }
                    }
                }
            }
        }
    }
}

// ---------------------------------------------------------------------------
// K2: combine E = 0.5*(Ea+Eb) + 0.5*(Y - Y^T) + eps I, mirror from lower.
// ---------------------------------------------------------------------------
__global__ void combine_E(const float* __restrict__ Y) {
    int idx = blockIdx.x * 256 + threadIdx.x;
    int i = idx >> 10, j = idx & 1023;
    if (i < j) return;
    float S = 0.5f * (g_Ea[idx] + g_Eb[idx]);
    float sk = 0.5f * (Y[i * NX + j] - Y[j * NX + i]);
    float ep = (i == j) ? EPSV : 0.f;
    float lo = S + sk + ep;
    g_E[i * NX + j] = lo;
    g_E[j * NX + i] = S - sk + ep;
    if (i == j) g_invd[i] = 1.0f / lo;
}

// ---------------------------------------------------------------------------
// K3: t1 = X1 @ xi ; K3b: s = X1 xi + X2 eps (3072 rows, warp per row)
// ---------------------------------------------------------------------------
__global__ void t1_kernel(const float* __restrict__ X, const float* __restrict__ xi) {
    int warp = threadIdx.x >> 5, lane = threadIdx.x & 31;
    int row = blockIdx.x * 8 + warp;
    const float* xr = X + (size_t)row * N3;
    float s = 0.f;
    for (int j = lane; j < NX; j += 32) s += xr[j] * xi[j];
    s = warp_sum(s);
    if (lane == 0) g_t1[row] = s;
}

__global__ void s_kernel(const float* __restrict__ X, const float* __restrict__ xi) {
    int warp = threadIdx.x >> 5, lane = threadIdx.x & 31;
    int row = blockIdx.x * 8 + warp;
    const float* xr = X + (size_t)row * N3;
    float s = 0.f;
    for (int j = lane; j < NX; j += 32) s += xr[j] * xi[j];
    for (int j = lane; j < NX; j += 32) s += xr[NX + j] * g_eps[j];
    s = warp_sum(s);
    if (lane == 0) g_s[row] = s;
}

// ---------------------------------------------------------------------------
// K4: transposed GEMV partials, grid (24 k-chunks, 4 col-groups)
// ---------------------------------------------------------------------------
__global__ void tgemv_part(const float* __restrict__ X, int colbase, int sel) {
    __shared__ float vs[128];
    const float* vec = sel ? g_s : g_t1;
    int kb = blockIdx.x, cg = blockIdx.y;
    int tid = threadIdx.x;
    if (tid < 128) vs[tid] = vec[kb * 128 + tid];
    __syncthreads();
    float acc = 0.f;
    const float* Xp = X + colbase + cg * 256 + tid + (size_t)kb * 128 * N3;
#pragma unroll 8
    for (int k = 0; k < 128; k++) acc += Xp[(size_t)k * N3] * vs[k];
    g_pp[kb][cg * 256 + tid] = acc;
}

// K5: reduce partials + dense 1024x512 GEMV
__global__ void tgemv_reduce(const float* __restrict__ M, const float* __restrict__ w,
                             float sign, int sel) {
    int warp = threadIdx.x >> 5, lane = threadIdx.x & 31;
    int row = blockIdx.x * 8 + warp;
    const float* mr = M + (size_t)row * 512;
    float s = 0.f;
    for (int j = lane; j < 512; j += 32) s += mr[j] * w[j];
    float pv = (lane < 24) ? g_pp[lane][row] : 0.f;
    float tot = warp_sum(s + sign * pv);
    if (lane == 0) {
        if (sel) g_r[0][row] = tot;
        else g_pre[row] = tot;
    }
}

// ---------------------------------------------------------------------------
// K6: blocked warp-serial scan.
// ---------------------------------------------------------------------------
__global__ __launch_bounds__(1024) void scan_kernel() {
    const int r = threadIdx.x;
    const int warp = r >> 5, lane = r & 31;
    __shared__ float s_eps[NX];
    __shared__ float s_accblk[32];
    const float* __restrict__ H22 = g_H22;
    const float pre = g_pre[r];
    float acc = 0.f;

    for (int b = 0; b < 32; b++) {
        const int base = b * 32;
        if (r >= base && r < base + 32) s_accblk[r - base] = pre + acc;
        __syncthreads();
        if (warp == 0) {
            float curj[32];
#pragma unroll
            for (int j = 0; j < 32; j++)
                curj[j] = H22[(size_t)(base + j) * NX + base + lane];
            const float myinvd = 1.0f / curj[lane];
            const float myv = s_accblk[lane] * myinvd;
#pragma unroll
            for (int j = 0; j < 32; j++) curj[j] *= myinvd;
            float accL = 0.f;
            float e = 0.f;
#pragma unroll
            for (int j = 0; j < 32; j++) {
                float v = myv + accL;
                float ex = __expf(2.0f * v);
                float el = 1.0f - __fdividef(2.0f, ex + 1.0f);
                float ej = __shfl_sync(0xffffffffu, el, j);
                if (lane == j) e = el;
                if (lane > j) accL -= curj[j] * ej;
            }
            s_eps[base + lane] = e;
            g_eps[base + lane] = e;
        }
        __syncthreads();
        if (r >= base + 32) {
#pragma unroll
            for (int j = 0; j < 32; j++)
                acc -= H22[(size_t)(base + j) * NX + r] * s_eps[base + j];
        }
    }
}

// ---------------------------------------------------------------------------
// K7: u = C2@xi + D21@eps + D22@w
// ---------------------------------------------------------------------------
__global__ void u_kernel(const float* __restrict__ xi, const float* __restrict__ w,
                         const float* __restrict__ C2, const float* __restrict__ D21,
                         const float* __restrict__ D22, float* __restrict__ out_u) {
    int warp = threadIdx.x >> 5, lane = threadIdx.x & 31;
    int row = blockIdx.x * 8 + warp;
    const float* c2 = C2 + (size_t)row * NX;
    const float* d21 = D21 + (size_t)row * NX;
    const float* d22 = D22 + (size_t)row * 512;
    float s = 0.f;
    for (int j = lane; j < NX; j += 32) s += c2[j] * xi[j] + d21[j] * g_eps[j];
    for (int j = lane; j < 512; j += 32) s += d22[j] * w[j];
    s = warp_sum(s);
    if (lane == 0) out_u[row] = s;
}

// ---------------------------------------------------------------------------
// K8: fused Chebyshev solve. One persistent kernel, 128 CTAs (single wave),
// software grid barrier between iterations. x/p/q live in registers (one row
// per warp); only r ping-pongs through gmem (cross-CTA reads via __ldcg).
// ---------------------------------------------------------------------------
struct ChebCoef { float al[NIT]; float be[NIT]; };

__global__ void cheb_reset() { g_barc = 0u; }

__global__ __launch_bounds__(256) void cheb_solve(float* __restrict__ x, ChebCoef cc) {
    __shared__ float zs[NX];
    const int tid = threadIdx.x;
    const int warp = tid >> 5, lane = tid & 31;
    const int row = blockIdx.x * 8 + warp;
    const float* __restrict__ Er = g_E + (size_t)row * NX;

    float xr = 0.f, pr = 0.f, qr = 0.f;

    for (int it = 0; it < NIT; it++) {
        const float* rin = g_r[it & 1];
        float* rout = g_r[(it & 1) ^ 1];
#pragma unroll
        for (int m = 0; m < 4; m++) {
            int j = tid + 256 * m;
            zs[j] = __ldcg(&rin[j]) * g_invd[j];
        }
        __syncthreads();
        float dot = 0.f;
#pragma unroll 4
        for (int j = lane; j < NX; j += 32) dot += Er[j] * zs[j];
        dot = warp_sum(dot);
        const float a = cc.al[it], be = cc.be[it];
        qr = dot + be * qr;
        pr = zs[row] + be * pr;
        xr += a * pr;
        if (it + 1 < NIT) {
            if (lane == 0) rout[row] = zs[row] * g_E[(size_t)row * NX + row] * 0.f
                                       + __ldcg(&rin[row]) - a * qr;
            // grid barrier
            __syncthreads();
            if (tid == 0) {
                __threadfence();
                atomicAdd(&g_barc, 1u);
                const unsigned target = (unsigned)((it + 1) * gridDim.x);
                while (atomicAdd(&g_barc, 0u) < target) {}
            }
            __syncthreads();
        }
    }
    if (lane == 0) x[row] = xr;
}

// ---------------------------------------------------------------------------
extern "C" void kernel_launch(void* const* d_in, const int* in_sizes, int n_in,
                              void* d_out, int out_size) {
    const float* w   = (const float*)d_in[1];
    const float* xi  = (const float*)d_in[2];
    const float* X   = (const float*)d_in[3];
    const float* Y   = (const float*)d_in[4];
    const float* B2  = (const float*)d_in[5];
    const float* C2  = (const float*)d_in[6];
    const float* D21 = (const float*)d_in[7];
    const float* D22 = (const float*)d_in[8];
    const float* D12 = (const float*)d_in[9];
    float* out = (float*)d_out;

    // Chebyshev scalars, spectrum of D^-1 E in [0.23, 2.15]
    const double lmin = 0.23, lmax = 2.15;
    const double th = 0.5 * (lmax + lmin), de = 0.5 * (lmax - lmin);
    ChebCoef cc;
    double ap = 0.0;
    for (int i = 0; i < NIT; i++) {
        double b, a;
        if (i == 0) { b = 0.0; a = 1.0 / th; }
        else { b = (de * ap * 0.5) * (de * ap * 0.5); a = 1.0 / (th - b / ap); }
        cc.al[i] = (float)a; cc.be[i] = (float)b; ap = a;
    }

    cudaFuncSetAttribute(mma_gemm, cudaFuncAttributeMaxDynamicSharedMemorySize, DSMEM_SZ);

    transpose_split<<<dim3(96, 96), dim3(32, 8)>>>(X);
    mma_gemm<<<108, 256, DSMEM_SZ>>>();
    combine_E<<<4096, 256>>>(Y);
    t1_kernel<<<384, 256>>>(X, xi);
    tgemv_part<<<dim3(24, 4), 256>>>(X, 1024, 0);
    tgemv_reduce<<<128, 256>>>(D12, w, -1.f, 0);
    scan_kernel<<<1, 1024>>>();
    s_kernel<<<384, 256>>>(X, xi);
    tgemv_part<<<dim3(24, 4), 256>>>(X, 2048, 1);
    tgemv_reduce<<<128, 256>>>(B2, w, 1.f, 1);
    u_kernel<<<64, 256>>>(xi, w, C2, D21, D22, out);

    cheb_reset<<<1, 1>>>();
    cheb_solve<<<128, 256>>>(out + 512, cc);
}